// round 11
// baseline (speedup 1.0000x reference)
#include <cuda_runtime.h>
#include <cstddef>

// Problem constants
constexpr int Bn = 8;
constexpr int S  = 160;
constexpr int D  = 256;
constexpr int RS = Bn * S;           // 1280 rows of x (flattened)
constexpr int P  = S * (S - 1) / 2;  // 12720 pairs

// Scratch (allocation-free __device__ globals)
__device__ float g_xa[RS * D];   // x@Wi + bias
__device__ float g_xb[RS * D];   // x@Wj

// ---------------------------------------------------------------------------
// Packed f32x2 helpers
// ---------------------------------------------------------------------------
__device__ __forceinline__ void ffma2(unsigned long long& d,
                                      unsigned long long a,
                                      unsigned long long b) {
    asm("fma.rn.f32x2 %0, %1, %2, %0;" : "+l"(d) : "l"(a), "l"(b));
}
__device__ __forceinline__ unsigned long long dup2(float x) {
    unsigned long long r;
    asm("mov.b64 %0, {%1, %1};" : "=l"(r) : "r"(__float_as_uint(x)));
    return r;
}
__device__ __forceinline__ unsigned long long add2(unsigned long long a,
                                                   unsigned long long b) {
    unsigned long long r;
    asm("add.rn.f32x2 %0, %1, %2;" : "=l"(r) : "l"(a), "l"(b));
    return r;
}
union F2U { unsigned long long u; float2 f; };
__device__ __forceinline__ float2 as_f2(unsigned long long v) { F2U t; t.u = v; return t.f; }

// ---------------------------------------------------------------------------
// Kernel 1: dual GEMM, M=1280, N=512 (Wi|Wj), K=256.
// BM=32, BN=32, BK=32, 128 threads, micro-tile 2 rows x 4 cols with
// accumulators PACKED OVER M: acc[c] = (out[r0][c], out[r1][c]).
//   a-operand = (x[r0][k], x[r1][k])  -> one LDS.64 from transposed x, NO MOV
//   b-operand = (w_c, w_c)            -> pre-splatted u64 in smem, LDS.128 x2
// Per k-step: 1 LDS.64 + 2 LDS.128 + 4 FFMA2 = 7 issue slots / 8 FMA cyc
// -> FMA-pipe bound at 87% issue. Grid (40,16)=640 blocks (~4.3/SM).
// ---------------------------------------------------------------------------
constexpr int BM = 32, BN = 32, BK = 32;
constexpr int NT = D / BK;  // 8 k-tiles

__global__ __launch_bounds__(128) void gemm_kernel(
    const float* __restrict__ x,
    const float* __restrict__ W,
    const float* __restrict__ bias)
{
    __shared__ float xs[2][BK][BM + 2];                        // transposed x tile
    __shared__ __align__(16) unsigned long long wsp[2][BK][BN + 2]; // W splat pairs

    const int t  = threadIdx.x;
    const int r0 = blockIdx.x * BM;
    const int by = blockIdx.y;
    const int half = by >> 3;                 // 0 -> Wi/g_xa, 1 -> Wj/g_xb
    const int c0 = (by & 7) * BN;             // column within the half
    const int wbase = half * D;               // W row base

    const float4* x4 = reinterpret_cast<const float4*>(x);
    const float4* W4 = reinterpret_cast<const float4*>(W);

    // compute mapping: rows 2*ty, 2*ty+1 ; cols 4*tx .. 4*tx+3
    const int ty = t >> 3;   // 0..15
    const int tx = t & 7;    // 0..7

    // staging mapping: 256 float4 per tile each for x and W -> 2 per thread
    const int row0 = t >> 3, ch0 = t & 7;           // idx t         (rows 0..15)
    const int row1 = row0 + 16, ch1 = ch0;          // idx t+128     (rows 16..31)

    unsigned long long acc[4];
    acc[0] = acc[1] = acc[2] = acc[3] = 0ull;

    float4 xv0, xv1, wv0, wv1;

    // prefetch tile 0
    xv0 = x4[(size_t)(r0 + row0) * 64 + ch0];
    xv1 = x4[(size_t)(r0 + row1) * 64 + ch1];
    wv0 = W4[(size_t)(wbase + row0) * 64 + (c0 >> 2) + ch0];
    wv1 = W4[(size_t)(wbase + row1) * 64 + (c0 >> 2) + ch1];

    // store tile 0
    xs[0][ch0 * 4 + 0][row0] = xv0.x;
    xs[0][ch0 * 4 + 1][row0] = xv0.y;
    xs[0][ch0 * 4 + 2][row0] = xv0.z;
    xs[0][ch0 * 4 + 3][row0] = xv0.w;
    xs[0][ch1 * 4 + 0][row1] = xv1.x;
    xs[0][ch1 * 4 + 1][row1] = xv1.y;
    xs[0][ch1 * 4 + 2][row1] = xv1.z;
    xs[0][ch1 * 4 + 3][row1] = xv1.w;
    *reinterpret_cast<ulonglong2*>(&wsp[0][row0][4 * ch0])     = make_ulonglong2(dup2(wv0.x), dup2(wv0.y));
    *reinterpret_cast<ulonglong2*>(&wsp[0][row0][4 * ch0 + 2]) = make_ulonglong2(dup2(wv0.z), dup2(wv0.w));
    *reinterpret_cast<ulonglong2*>(&wsp[0][row1][4 * ch1])     = make_ulonglong2(dup2(wv1.x), dup2(wv1.y));
    *reinterpret_cast<ulonglong2*>(&wsp[0][row1][4 * ch1 + 2]) = make_ulonglong2(dup2(wv1.z), dup2(wv1.w));
    __syncthreads();

    #pragma unroll 1
    for (int kt = 0; kt < NT; kt++) {
        const int cur = kt & 1;
        const int nxt = cur ^ 1;

        if (kt + 1 < NT) {  // global prefetch into registers
            const int kc = (kt + 1) * (BK / 4);
            xv0 = x4[(size_t)(r0 + row0) * 64 + kc + ch0];
            xv1 = x4[(size_t)(r0 + row1) * 64 + kc + ch1];
            wv0 = W4[(size_t)(wbase + (kt + 1) * BK + row0) * 64 + (c0 >> 2) + ch0];
            wv1 = W4[(size_t)(wbase + (kt + 1) * BK + row1) * 64 + (c0 >> 2) + ch1];
        }

        #pragma unroll
        for (int k = 0; k < BK; k++) {
            // one LDS.64: a-pair (x[r0][k], x[r1][k]) -- rows 2ty, 2ty+1
            const unsigned long long ap =
                *reinterpret_cast<const unsigned long long*>(&xs[cur][k][2 * ty]);
            // two LDS.128: four pre-splatted W pairs (cols 4tx..4tx+3)
            const ulonglong2 w01 = *reinterpret_cast<const ulonglong2*>(&wsp[cur][k][4 * tx]);
            const ulonglong2 w23 = *reinterpret_cast<const ulonglong2*>(&wsp[cur][k][4 * tx + 2]);
            ffma2(acc[0], ap, w01.x);
            ffma2(acc[1], ap, w01.y);
            ffma2(acc[2], ap, w23.x);
            ffma2(acc[3], ap, w23.y);
        }

        if (kt + 1 < NT) {
            xs[nxt][ch0 * 4 + 0][row0] = xv0.x;
            xs[nxt][ch0 * 4 + 1][row0] = xv0.y;
            xs[nxt][ch0 * 4 + 2][row0] = xv0.z;
            xs[nxt][ch0 * 4 + 3][row0] = xv0.w;
            xs[nxt][ch1 * 4 + 0][row1] = xv1.x;
            xs[nxt][ch1 * 4 + 1][row1] = xv1.y;
            xs[nxt][ch1 * 4 + 2][row1] = xv1.z;
            xs[nxt][ch1 * 4 + 3][row1] = xv1.w;
            *reinterpret_cast<ulonglong2*>(&wsp[nxt][row0][4 * ch0])     = make_ulonglong2(dup2(wv0.x), dup2(wv0.y));
            *reinterpret_cast<ulonglong2*>(&wsp[nxt][row0][4 * ch0 + 2]) = make_ulonglong2(dup2(wv0.z), dup2(wv0.w));
            *reinterpret_cast<ulonglong2*>(&wsp[nxt][row1][4 * ch1])     = make_ulonglong2(dup2(wv1.x), dup2(wv1.y));
            *reinterpret_cast<ulonglong2*>(&wsp[nxt][row1][4 * ch1 + 2]) = make_ulonglong2(dup2(wv1.z), dup2(wv1.w));
            __syncthreads();
        }
    }

    // epilogue: unpack M-packed accumulators, add bias on Wi half
    const int cc = c0 + 4 * tx;
    float4 bvec = make_float4(0.f, 0.f, 0.f, 0.f);
    if (!half) bvec = *reinterpret_cast<const float4*>(&bias[cc]);
    float* dst = half ? g_xb : g_xa;

    const float2 f0 = as_f2(acc[0]);
    const float2 f1 = as_f2(acc[1]);
    const float2 f2 = as_f2(acc[2]);
    const float2 f3 = as_f2(acc[3]);
    const int rowe = r0 + 2 * ty;
    *reinterpret_cast<float4*>(&dst[(size_t)rowe * D + cc]) =
        make_float4(f0.x + bvec.x, f1.x + bvec.y, f2.x + bvec.z, f3.x + bvec.w);
    *reinterpret_cast<float4*>(&dst[(size_t)(rowe + 1) * D + cc]) =
        make_float4(f0.y + bvec.x, f1.y + bvec.y, f2.y + bvec.z, f3.y + bvec.w);
}

// ---------------------------------------------------------------------------
// Kernel 2: pairwise expansion (unchanged; measured stable 18.4-18.5us,
// near the steady-state DRAM writeback floor).
// ---------------------------------------------------------------------------
constexpr int TI  = 16;
constexpr int TPD = S / TI;                      // 10
constexpr int NTILES = TPD * (TPD + 1) / 2;      // 55

__global__ __launch_bounds__(256) void expand_kernel(float* __restrict__ out)
{
    __shared__ float4 sb[TI][32];

    int rem = blockIdx.x, ti = 0;
    while (rem >= TPD - ti) { rem -= TPD - ti; ti++; }
    const int tj = ti + rem;

    const int b   = blockIdx.y;
    const int h   = blockIdx.z;   // D half
    const int i0  = ti * TI;
    const int j0  = tj * TI;
    const int tid = threadIdx.x;
    const int warp = tid >> 5;
    const int lane = tid & 31;

    const float4* xa4 = reinterpret_cast<const float4*>(g_xa);
    const float4* xb4 = reinterpret_cast<const float4*>(g_xb);

    #pragma unroll
    for (int q = 0; q < 2; q++) {
        const int k = tid + q * 256;
        const int r = k >> 5, c = k & 31;
        sb[r][c] = xb4[(size_t)(b * S + j0 + r) * 64 + h * 32 + c];
    }

    const int ia = i0 + 2 * warp;
    const int ib = ia + 1;
    const float4 A0 = xa4[(size_t)(b * S + ia) * 64 + h * 32 + lane];
    const float4 A1 = xa4[(size_t)(b * S + ib) * 64 + h * 32 + lane];
    F2U a0lo, a0hi, a1lo, a1hi;
    a0lo.f = make_float2(A0.x, A0.y); a0hi.f = make_float2(A0.z, A0.w);
    a1lo.f = make_float2(A1.x, A1.y); a1hi.f = make_float2(A1.z, A1.w);

    __syncthreads();

    const int p0 = ((2 * S - 1 - ia) * ia) / 2 + j0 - ia - 1;
    const int p1 = ((2 * S - 1 - ib) * ib) / 2 + j0 - ib - 1;

    float4* out4 = reinterpret_cast<float4*>(out);
    float4* o0 = out4 + ((size_t)b * P + p0) * 64 + h * 32 + lane;
    float4* o1 = out4 + ((size_t)b * P + p1) * 64 + h * 32 + lane;

    #pragma unroll
    for (int jj = 0; jj < TI; jj++) {
        const float4 v = sb[jj][lane];
        F2U vlo, vhi;
        vlo.f = make_float2(v.x, v.y);
        vhi.f = make_float2(v.z, v.w);
        const int j = j0 + jj;

        if (j > ia) {
            F2U rlo, rhi;
            rlo.u = add2(a0lo.u, vlo.u);
            rhi.u = add2(a0hi.u, vhi.u);
            o0[(size_t)jj * 64] = make_float4(rlo.f.x, rlo.f.y, rhi.f.x, rhi.f.y);
        }
        if (j > ib) {
            F2U rlo, rhi;
            rlo.u = add2(a1lo.u, vlo.u);
            rhi.u = add2(a1hi.u, vhi.u);
            o1[(size_t)jj * 64] = make_float4(rlo.f.x, rlo.f.y, rhi.f.x, rhi.f.y);
        }
    }
}

// ---------------------------------------------------------------------------
extern "C" void kernel_launch(void* const* d_in, const int* in_sizes, int n_in,
                              void* d_out, int out_size)
{
    const float* x    = (const float*)d_in[0];   // (8,160,256) f32
    const float* W    = (const float*)d_in[1];   // (512,256)   f32
    const float* bias = (const float*)d_in[2];   // (256,)      f32
    float* out = (float*)d_out;                  // (8,12720,256) f32

    gemm_kernel<<<dim3(RS / BM, 2 * D / BN), 128>>>(x, W, bias);
    expand_kernel<<<dim3(NTILES, Bn, 2), 256>>>(out);
}

// round 12
// speedup vs baseline: 1.7438x; 1.7438x over previous
#include <cuda_runtime.h>
#include <cstddef>

// Problem constants
constexpr int Bn = 8;
constexpr int S  = 160;
constexpr int D  = 256;
constexpr int RS = Bn * S;           // 1280 rows of x (flattened)
constexpr int P  = S * (S - 1) / 2;  // 12720 pairs

// Scratch (allocation-free __device__ globals)
__device__ float g_xa[RS * D];   // x@Wi + bias
__device__ float g_xb[RS * D];   // x@Wj

// ---------------------------------------------------------------------------
// Packed f32x2 helpers
// ---------------------------------------------------------------------------
__device__ __forceinline__ void ffma2(unsigned long long& d,
                                      unsigned long long a,
                                      unsigned long long b) {
    asm("fma.rn.f32x2 %0, %1, %2, %0;" : "+l"(d) : "l"(a), "l"(b));
}
__device__ __forceinline__ unsigned long long dup2(float x) {
    unsigned long long r;
    asm("mov.b64 %0, {%1, %1};" : "=l"(r) : "r"(__float_as_uint(x)));
    return r;
}
__device__ __forceinline__ unsigned long long add2(unsigned long long a,
                                                   unsigned long long b) {
    unsigned long long r;
    asm("add.rn.f32x2 %0, %1, %2;" : "=l"(r) : "l"(a), "l"(b));
    return r;
}
union F2U { unsigned long long u; float2 f; };
__device__ __forceinline__ float2 as_f2(unsigned long long v) { F2U t; t.u = v; return t.f; }

// ---------------------------------------------------------------------------
// Kernel 1: dual GEMM, M=1280, N=512 (Wi|Wj), K=256.
// R9 inner loop/micro-tile (2 rows x 4 cols, 1 LDS.64 + 1 LDS.128 + 2 MOV +
// 4 FFMA2 per k-step), BM=BN=BK=32, 128 threads, grid (40,16)=640 blocks.
// NEW: 3-stage smem ring + prefetch distance 2 -- the STS of tile kt+1 uses
// data LDG'd a full compute-loop + barrier earlier, hiding L2/DRAM latency.
// ---------------------------------------------------------------------------
constexpr int BM = 32, BN = 32, BK = 32;
constexpr int NT = D / BK;  // 8 k-tiles
constexpr int NSTG = 3;

__global__ __launch_bounds__(128) void gemm_kernel(
    const float* __restrict__ x,
    const float* __restrict__ W,
    const float* __restrict__ bias)
{
    __shared__ float xs[NSTG][BK][BM + 2];               // transposed x tiles
    __shared__ __align__(16) float ws[NSTG][BK][BN + 4]; // W tiles

    const int t  = threadIdx.x;
    const int r0 = blockIdx.x * BM;
    const int by = blockIdx.y;
    const int half = by >> 3;                 // 0 -> Wi/g_xa, 1 -> Wj/g_xb
    const int c0 = (by & 7) * BN;             // column within the half
    const int wbase = half * D;               // W row base

    const float4* x4 = reinterpret_cast<const float4*>(x);
    const float4* W4 = reinterpret_cast<const float4*>(W);

    // compute mapping: rows 2*ty, 2*ty+1 ; cols 4*tx .. 4*tx+3
    const int ty = t >> 3;   // 0..15
    const int tx = t & 7;    // 0..7

    // staging mapping: 256 float4 per tile each for x and W -> 2 per thread
    const int row0 = t >> 3, ch0 = t & 7;     // rows 0..15
    const int row1 = row0 + 16;               // rows 16..31

    unsigned long long acc[2][2];
    acc[0][0] = acc[0][1] = acc[1][0] = acc[1][1] = 0ull;

    // two register prefetch sets (A, B)
    float4 xA0, xA1, wA0, wA1;
    float4 xB0, xB1, wB0, wB1;

    // ---- prologue: tile0 -> A -> stage0 ; tile1 -> B ----
    xA0 = x4[(size_t)(r0 + row0) * 64 + 0 + ch0];
    xA1 = x4[(size_t)(r0 + row1) * 64 + 0 + ch0];
    wA0 = W4[(size_t)(wbase + row0) * 64 + (c0 >> 2) + ch0];
    wA1 = W4[(size_t)(wbase + row1) * 64 + (c0 >> 2) + ch0];

    xs[0][ch0 * 4 + 0][row0] = xA0.x;
    xs[0][ch0 * 4 + 1][row0] = xA0.y;
    xs[0][ch0 * 4 + 2][row0] = xA0.z;
    xs[0][ch0 * 4 + 3][row0] = xA0.w;
    xs[0][ch0 * 4 + 0][row1] = xA1.x;
    xs[0][ch0 * 4 + 1][row1] = xA1.y;
    xs[0][ch0 * 4 + 2][row1] = xA1.z;
    xs[0][ch0 * 4 + 3][row1] = xA1.w;
    *reinterpret_cast<float4*>(&ws[0][row0][ch0 * 4]) = wA0;
    *reinterpret_cast<float4*>(&ws[0][row1][ch0 * 4]) = wA1;

    xB0 = x4[(size_t)(r0 + row0) * 64 + 8 + ch0];
    xB1 = x4[(size_t)(r0 + row1) * 64 + 8 + ch0];
    wB0 = W4[(size_t)(wbase + BK + row0) * 64 + (c0 >> 2) + ch0];
    wB1 = W4[(size_t)(wbase + BK + row1) * 64 + (c0 >> 2) + ch0];
    __syncthreads();

    #pragma unroll 1
    for (int kt = 0; kt < NT; kt++) {
        const int s_cur = kt % NSTG;
        const int s_nxt = (kt + 1) % NSTG;
        const bool even = ((kt & 1) == 0);

        // 1. prefetch tile kt+2 into the set NOT holding tile kt+1
        if (kt + 2 < NT) {
            const int kc = (kt + 2) * 8;                    // float4 col offset
            const int wr = wbase + (kt + 2) * BK;
            if (even) {
                xA0 = x4[(size_t)(r0 + row0) * 64 + kc + ch0];
                xA1 = x4[(size_t)(r0 + row1) * 64 + kc + ch0];
                wA0 = W4[(size_t)(wr + row0) * 64 + (c0 >> 2) + ch0];
                wA1 = W4[(size_t)(wr + row1) * 64 + (c0 >> 2) + ch0];
            } else {
                xB0 = x4[(size_t)(r0 + row0) * 64 + kc + ch0];
                xB1 = x4[(size_t)(r0 + row1) * 64 + kc + ch0];
                wB0 = W4[(size_t)(wr + row0) * 64 + (c0 >> 2) + ch0];
                wB1 = W4[(size_t)(wr + row1) * 64 + (c0 >> 2) + ch0];
            }
        }

        // 2. store tile kt+1 (LDG'd one full iteration ago) into stage s_nxt
        if (kt + 1 < NT) {
            const float4 sx0 = even ? xB0 : xA0;
            const float4 sx1 = even ? xB1 : xA1;
            const float4 sw0 = even ? wB0 : wA0;
            const float4 sw1 = even ? wB1 : wA1;
            xs[s_nxt][ch0 * 4 + 0][row0] = sx0.x;
            xs[s_nxt][ch0 * 4 + 1][row0] = sx0.y;
            xs[s_nxt][ch0 * 4 + 2][row0] = sx0.z;
            xs[s_nxt][ch0 * 4 + 3][row0] = sx0.w;
            xs[s_nxt][ch0 * 4 + 0][row1] = sx1.x;
            xs[s_nxt][ch0 * 4 + 1][row1] = sx1.y;
            xs[s_nxt][ch0 * 4 + 2][row1] = sx1.z;
            xs[s_nxt][ch0 * 4 + 3][row1] = sx1.w;
            *reinterpret_cast<float4*>(&ws[s_nxt][row0][ch0 * 4]) = sw0;
            *reinterpret_cast<float4*>(&ws[s_nxt][row1][ch0 * 4]) = sw1;
        }

        // 3. compute on stage s_cur (R9 inner loop, unchanged)
        #pragma unroll
        for (int k = 0; k < BK; k++) {
            const float2 a2 = *reinterpret_cast<const float2*>(&xs[s_cur][k][2 * ty]);
            const ulonglong2 wq = *reinterpret_cast<const ulonglong2*>(&ws[s_cur][k][4 * tx]);
            const unsigned long long a0 = dup2(a2.x);
            const unsigned long long a1 = dup2(a2.y);
            ffma2(acc[0][0], a0, wq.x); ffma2(acc[0][1], a0, wq.y);
            ffma2(acc[1][0], a1, wq.x); ffma2(acc[1][1], a1, wq.y);
        }

        // 4. barrier: s_nxt ready for next iter; stage reuse is 2 barriers away
        __syncthreads();
    }

    // epilogue: bias on Wi half, one STG.128 per row (R9, unchanged)
    const int cc = c0 + 4 * tx;
    float4 bvec = make_float4(0.f, 0.f, 0.f, 0.f);
    if (!half) bvec = *reinterpret_cast<const float4*>(&bias[cc]);
    float* dst = half ? g_xb : g_xa;
    #pragma unroll
    for (int r = 0; r < 2; r++) {
        const int row = r0 + 2 * ty + r;
        const float2 f0 = as_f2(acc[r][0]);
        const float2 f1 = as_f2(acc[r][1]);
        *reinterpret_cast<float4*>(&dst[(size_t)row * D + cc]) =
            make_float4(f0.x + bvec.x, f0.y + bvec.y, f1.x + bvec.z, f1.y + bvec.w);
    }
}

// ---------------------------------------------------------------------------
// Kernel 2: pairwise expansion (R9 verbatim; measured stable 18.4-18.6us).
// ---------------------------------------------------------------------------
constexpr int TI  = 16;
constexpr int TPD = S / TI;                      // 10
constexpr int NTILES = TPD * (TPD + 1) / 2;      // 55

__global__ __launch_bounds__(256) void expand_kernel(float* __restrict__ out)
{
    __shared__ float4 sb[TI][32];

    int rem = blockIdx.x, ti = 0;
    while (rem >= TPD - ti) { rem -= TPD - ti; ti++; }
    const int tj = ti + rem;

    const int b   = blockIdx.y;
    const int h   = blockIdx.z;   // D half
    const int i0  = ti * TI;
    const int j0  = tj * TI;
    const int tid = threadIdx.x;
    const int warp = tid >> 5;
    const int lane = tid & 31;

    const float4* xa4 = reinterpret_cast<const float4*>(g_xa);
    const float4* xb4 = reinterpret_cast<const float4*>(g_xb);

    #pragma unroll
    for (int q = 0; q < 2; q++) {
        const int k = tid + q * 256;
        const int r = k >> 5, c = k & 31;
        sb[r][c] = xb4[(size_t)(b * S + j0 + r) * 64 + h * 32 + c];
    }

    const int ia = i0 + 2 * warp;
    const int ib = ia + 1;
    const float4 A0 = xa4[(size_t)(b * S + ia) * 64 + h * 32 + lane];
    const float4 A1 = xa4[(size_t)(b * S + ib) * 64 + h * 32 + lane];
    F2U a0lo, a0hi, a1lo, a1hi;
    a0lo.f = make_float2(A0.x, A0.y); a0hi.f = make_float2(A0.z, A0.w);
    a1lo.f = make_float2(A1.x, A1.y); a1hi.f = make_float2(A1.z, A1.w);

    __syncthreads();

    const int p0 = ((2 * S - 1 - ia) * ia) / 2 + j0 - ia - 1;
    const int p1 = ((2 * S - 1 - ib) * ib) / 2 + j0 - ib - 1;

    float4* out4 = reinterpret_cast<float4*>(out);
    float4* o0 = out4 + ((size_t)b * P + p0) * 64 + h * 32 + lane;
    float4* o1 = out4 + ((size_t)b * P + p1) * 64 + h * 32 + lane;

    #pragma unroll
    for (int jj = 0; jj < TI; jj++) {
        const float4 v = sb[jj][lane];
        F2U vlo, vhi;
        vlo.f = make_float2(v.x, v.y);
        vhi.f = make_float2(v.z, v.w);
        const int j = j0 + jj;

        if (j > ia) {
            F2U rlo, rhi;
            rlo.u = add2(a0lo.u, vlo.u);
            rhi.u = add2(a0hi.u, vhi.u);
            o0[(size_t)jj * 64] = make_float4(rlo.f.x, rlo.f.y, rhi.f.x, rhi.f.y);
        }
        if (j > ib) {
            F2U rlo, rhi;
            rlo.u = add2(a1lo.u, vlo.u);
            rhi.u = add2(a1hi.u, vhi.u);
            o1[(size_t)jj * 64] = make_float4(rlo.f.x, rlo.f.y, rhi.f.x, rhi.f.y);
        }
    }
}

// ---------------------------------------------------------------------------
extern "C" void kernel_launch(void* const* d_in, const int* in_sizes, int n_in,
                              void* d_out, int out_size)
{
    const float* x    = (const float*)d_in[0];   // (8,160,256) f32
    const float* W    = (const float*)d_in[1];   // (512,256)   f32
    const float* bias = (const float*)d_in[2];   // (256,)      f32
    float* out = (float*)d_out;                  // (8,12720,256) f32

    gemm_kernel<<<dim3(RS / BM, 2 * D / BN), 128>>>(x, W, bias);
    expand_kernel<<<dim3(NTILES, Bn, 2), 256>>>(out);
}